// round 3
// baseline (speedup 1.0000x reference)
#include <cuda_runtime.h>

// EmbeddingLayer: 16 sparse gathers + 2 sequence poolings (sum, nonzero-mean) + dense concat.
//
// R3: uniform-work blocks. grid=2048, block=256; each block fully produces 2
// output rows (sparse copy + both seq poolings + dense). Pooling chain per
// thread is 12-13 gathers (4 segments per feature), merged with shfl_xor(16)
// within a warp and a small smem reduce across the warp pair.

#define VOCAB   100000
#define BATCH   4096
#define EMBED   64
#define SEQLEN  50
#define NSPARSE 16
#define NDENSE  13
#define ROW_OUT (NSPARSE * EMBED + 2 * EMBED + NDENSE)  // 1165

#define THREADS 256
#define ROWS_PER_BLOCK 2
#define GRID (BATCH / ROWS_PER_BLOCK)   // 2048

__global__ __launch_bounds__(THREADS)
void embedding_layer_kernel(const float4* __restrict__ sp_tab,   // [16*VOCAB*16] float4
                            const float4* __restrict__ seq_tab,  // [ 2*VOCAB*16] float4
                            const float*  __restrict__ dense,    // [BATCH*13]
                            const int*    __restrict__ sp_idx,   // [16*BATCH]
                            const int*    __restrict__ sq_idx,   // [2*BATCH*50]
                            float*        __restrict__ out)      // [BATCH*1165]
{
    __shared__ float4 s_acc[ROWS_PER_BLOCK][2][16];  // upper-warp partial sums
    __shared__ float4 s_cnt[ROWS_PER_BLOCK][16];     // upper-warp nonzero counts (feat 1)

    const int tid = threadIdx.x;
    const int lr  = tid >> 7;            // local row 0..1
    const int t   = tid & 127;           // thread within row-group
    const int q   = t & 15;              // float4 lane within embed dim
    const int b   = blockIdx.x * ROWS_PER_BLOCK + lr;

    float* __restrict__ orow = out + (size_t)b * ROW_OUT;

    // ---- sparse: 2 features per thread (f and f+8), independent LDG.128 ----
    const int fg = t >> 4;               // 0..7
    #pragma unroll
    for (int k = 0; k < 2; k++) {
        const int f = fg + k * 8;
        int idx = __ldg(&sp_idx[f * BATCH + b]);
        float4 v = __ldg(&sp_tab[((size_t)f * VOCAB + idx) * 16 + q]);
        float* o = orow + f * EMBED + q * 4;
        o[0] = v.x; o[1] = v.y; o[2] = v.z; o[3] = v.w;
    }

    // ---- dense tail ----
    if (t < NDENSE)
        orow[(NSPARSE + 2) * EMBED + t] = __ldg(&dense[(size_t)b * NDENSE + t]);

    // ---- seq pooling: seg 0..7 -> feat = seg>>2, quarter s4 = seg&3 ----
    // quarter s4 covers seq entries [start, end): lengths {13,13,12,12}
    const int seg  = t >> 4;
    const int feat = seg >> 2;           // uniform per warp
    const int s4   = seg & 3;
    const int start = s4 * 12 + (s4 < 2 ? s4 : 2);           // 0,13,26,38
    const int end   = (s4 + 1) * 12 + (s4 >= 1 ? 2 : 1);     // 13,26,38,50

    const int* __restrict__ ip =
        sq_idx + ((size_t)feat * BATCH + b) * SEQLEN;
    const float4* __restrict__ tab = seq_tab + (size_t)feat * VOCAB * 16;

    float4 acc = make_float4(0.f, 0.f, 0.f, 0.f);
    float4 c4  = make_float4(0.f, 0.f, 0.f, 0.f);

    #pragma unroll
    for (int s = 0; s < 13; s++) {
        int ss = start + s;
        if (ss < end) {
            int idx = __ldg(&ip[ss]);
            float4 v = __ldg(&tab[(size_t)idx * 16 + q]);
            acc.x += v.x; acc.y += v.y; acc.z += v.z; acc.w += v.w;
            if (feat) {
                c4.x += (v.x != 0.f) ? 1.f : 0.f;
                c4.y += (v.y != 0.f) ? 1.f : 0.f;
                c4.z += (v.z != 0.f) ? 1.f : 0.f;
                c4.w += (v.w != 0.f) ? 1.f : 0.f;
            }
        }
    }

    // merge quarter pairs within the warp (lanes l and l^16 share q)
    acc.x += __shfl_xor_sync(0xFFFFFFFFu, acc.x, 16);
    acc.y += __shfl_xor_sync(0xFFFFFFFFu, acc.y, 16);
    acc.z += __shfl_xor_sync(0xFFFFFFFFu, acc.z, 16);
    acc.w += __shfl_xor_sync(0xFFFFFFFFu, acc.w, 16);
    if (feat) {
        c4.x += __shfl_xor_sync(0xFFFFFFFFu, c4.x, 16);
        c4.y += __shfl_xor_sync(0xFFFFFFFFu, c4.y, 16);
        c4.z += __shfl_xor_sync(0xFFFFFFFFu, c4.z, 16);
        c4.w += __shfl_xor_sync(0xFFFFFFFFu, c4.w, 16);
    }

    // cross-warp merge: warp pair (lower = quarters 0,1; upper = quarters 2,3)
    const int wupper = (t >> 5) & 1;
    if (((t & 31) < 16) && wupper) {
        s_acc[lr][feat][q] = acc;
        if (feat) s_cnt[lr][q] = c4;
    }
    __syncthreads();
    if (((t & 31) < 16) && !wupper) {
        float4 p = s_acc[lr][feat][q];
        acc.x += p.x; acc.y += p.y; acc.z += p.z; acc.w += p.w;
        float* o = orow + (NSPARSE + feat) * EMBED + q * 4;
        if (feat == 0) {
            o[0] = acc.x; o[1] = acc.y; o[2] = acc.z; o[3] = acc.w;
        } else {
            float4 pc = s_cnt[lr][q];
            c4.x += pc.x; c4.y += pc.y; c4.z += pc.z; c4.w += pc.w;
            o[0] = acc.x / (c4.x + 1e-16f);
            o[1] = acc.y / (c4.y + 1e-16f);
            o[2] = acc.z / (c4.z + 1e-16f);
            o[3] = acc.w / (c4.w + 1e-16f);
        }
    }
}

extern "C" void kernel_launch(void* const* d_in, const int* in_sizes, int n_in,
                              void* d_out, int out_size) {
    const float* sp_tab  = (const float*)d_in[0];
    const float* seq_tab = (const float*)d_in[1];
    const float* dense   = (const float*)d_in[2];
    const int*   sp_idx  = (const int*)d_in[3];
    const int*   sq_idx  = (const int*)d_in[4];
    float*       out     = (float*)d_out;

    embedding_layer_kernel<<<GRID, THREADS>>>(
        (const float4*)sp_tab, (const float4*)seq_tab, dense, sp_idx, sq_idx, out);
}

// round 4
// speedup vs baseline: 1.2166x; 1.2166x over previous
#include <cuda_runtime.h>

// EmbeddingLayer: 16 sparse gathers + 2 sequence poolings (sum, nonzero-mean) + dense concat.
//
// R4 = R2 structure (best so far) with two latency fixes:
//   - seq-pooling blocks FIRST in the grid (long pole starts in wave 1,
//     1-gather sparse blocks backfill).
//   - pooling gathers: all 25 indices preloaded into registers, gather loop
//     fully unrolled, __launch_bounds__(256,4) raises reg budget to 64 so
//     ptxas can keep ~2x more LDG.128 in flight per thread.

#define VOCAB   100000
#define BATCH   4096
#define EMBED   64
#define SEQLEN  50
#define NSPARSE 16
#define NDENSE  13
#define ROW_OUT (NSPARSE * EMBED + 2 * EMBED + NDENSE)  // 1165

#define SEQ_ROWS_PER_BLOCK 4                          // 4 rows x 2 feats = 8 warps
#define SEQ_BLOCKS (BATCH / SEQ_ROWS_PER_BLOCK)       // 1024  (blockIdx 0..1023)
#define SPARSE_BLOCKS BATCH                           // 4096  (blockIdx 1024..5119)
#define THREADS 256
#define HALF_SEQ (SEQLEN / 2)                         // 25

__global__ __launch_bounds__(THREADS, 4)
void embedding_layer_kernel(const float4* __restrict__ sp_tab,   // [16*VOCAB*16] float4
                            const float4* __restrict__ seq_tab,  // [ 2*VOCAB*16] float4
                            const float*  __restrict__ dense,    // [BATCH*13]
                            const int*    __restrict__ sp_idx,   // [16*BATCH]
                            const int*    __restrict__ sq_idx,   // [2*BATCH*50]
                            float*        __restrict__ out)      // [BATCH*1165]
{
    const int tid = threadIdx.x;

    if (blockIdx.x < SEQ_BLOCKS) {
        // ---- seq pooling: one warp per (batch row, feature) ----
        const int warp = tid >> 5;                       // 0..7
        const int lane = tid & 31;
        const int b    = blockIdx.x * SEQ_ROWS_PER_BLOCK + (warp >> 1);
        const int feat = warp & 1;                       // 0: sum, 1: nonzero-mean
        const int q    = lane & 15;                      // float4 lane in embed dim
        const int half = lane >> 4;                      // 0 -> [0,25), 1 -> [25,50)

        const int* __restrict__ ip =
            sq_idx + ((size_t)feat * BATCH + b) * SEQLEN + half * HALF_SEQ;
        const float4* __restrict__ tab = seq_tab + (size_t)feat * VOCAB * 16;

        // preload all indices -> gather loop is pure independent LDG.128s
        int idxs[HALF_SEQ];
        #pragma unroll
        for (int s = 0; s < HALF_SEQ; s++) idxs[s] = __ldg(&ip[s]);

        float4 acc = make_float4(0.f, 0.f, 0.f, 0.f);
        float4 cnt = make_float4(0.f, 0.f, 0.f, 0.f);

        #pragma unroll
        for (int s = 0; s < HALF_SEQ; s++) {
            float4 v = __ldg(&tab[(size_t)idxs[s] * 16 + q]);
            acc.x += v.x; acc.y += v.y; acc.z += v.z; acc.w += v.w;
            if (feat) {
                cnt.x += (v.x != 0.f) ? 1.f : 0.f;
                cnt.y += (v.y != 0.f) ? 1.f : 0.f;
                cnt.z += (v.z != 0.f) ? 1.f : 0.f;
                cnt.w += (v.w != 0.f) ? 1.f : 0.f;
            }
        }

        // merge the two seq-halves (lanes l and l^16 share q)
        acc.x += __shfl_xor_sync(0xFFFFFFFFu, acc.x, 16);
        acc.y += __shfl_xor_sync(0xFFFFFFFFu, acc.y, 16);
        acc.z += __shfl_xor_sync(0xFFFFFFFFu, acc.z, 16);
        acc.w += __shfl_xor_sync(0xFFFFFFFFu, acc.w, 16);
        if (feat) {
            cnt.x += __shfl_xor_sync(0xFFFFFFFFu, cnt.x, 16);
            cnt.y += __shfl_xor_sync(0xFFFFFFFFu, cnt.y, 16);
            cnt.z += __shfl_xor_sync(0xFFFFFFFFu, cnt.z, 16);
            cnt.w += __shfl_xor_sync(0xFFFFFFFFu, cnt.w, 16);
        }

        if (half == 0) {
            float* o = out + (size_t)b * ROW_OUT + (NSPARSE + feat) * EMBED + q * 4;
            if (feat == 0) {
                o[0] = acc.x; o[1] = acc.y; o[2] = acc.z; o[3] = acc.w;
            } else {
                o[0] = acc.x / (cnt.x + 1e-16f);
                o[1] = acc.y / (cnt.y + 1e-16f);
                o[2] = acc.z / (cnt.z + 1e-16f);
                o[3] = acc.w / (cnt.w + 1e-16f);
            }
        }
    } else {
        // ---- sparse copy + dense tail: one block per batch row ----
        const int b = blockIdx.x - SEQ_BLOCKS;
        const int f = tid >> 4;      // feature 0..15
        const int q = tid & 15;      // float4 lane 0..15

        float* __restrict__ orow = out + (size_t)b * ROW_OUT;

        int idx = __ldg(&sp_idx[f * BATCH + b]);
        float4 v = __ldg(&sp_tab[((size_t)f * VOCAB + idx) * 16 + q]);
        float* o = orow + f * EMBED + q * 4;
        o[0] = v.x; o[1] = v.y; o[2] = v.z; o[3] = v.w;

        if (tid < NDENSE)
            orow[(NSPARSE + 2) * EMBED + tid] = __ldg(&dense[(size_t)b * NDENSE + tid]);
    }
}

extern "C" void kernel_launch(void* const* d_in, const int* in_sizes, int n_in,
                              void* d_out, int out_size) {
    const float* sp_tab  = (const float*)d_in[0];
    const float* seq_tab = (const float*)d_in[1];
    const float* dense   = (const float*)d_in[2];
    const int*   sp_idx  = (const int*)d_in[3];
    const int*   sq_idx  = (const int*)d_in[4];
    float*       out     = (float*)d_out;

    dim3 grid(SEQ_BLOCKS + SPARSE_BLOCKS);  // 5120 blocks, pooling first
    dim3 block(THREADS);
    embedding_layer_kernel<<<grid, block>>>(
        (const float4*)sp_tab, (const float4*)seq_tab, dense, sp_idx, sq_idx, out);
}